// round 13
// baseline (speedup 1.0000x reference)
#include <cuda_runtime.h>
#include <cuda_fp16.h>
#include <cstdint>

#define HW 4096
#define CHWX ((long)256 * HW)

// float offsets in g_scratch
#define OFF_GP    35651584L
#define OFF_WTO0  37748736L
#define OFF_WTO1  38338560L
#define OFF_WTQ   38928384L
#define OFF_WTV   40108032L
#define OFF_WTK   41287680L
#define OFF_XTP   42467328L
#define OFF_YTO   47185920L
#define OFF_XT    56623104L
#define OFF_YT    132120576L
#define OFF_YTK   207618048L
__device__ __align__(256) float g_scratch[212336640];

#define XT_PLANE_B  8388608L
#define XTP_PLANE_B 524288L
#define YT_PLANE    1048576L
#define YT_SET      37748736L
#define YTK_PLANE   131072L
#define YTO_PLANE   131072L
#define YTO_HALF    4718592L

#define LO_SCALE    1024.f
#define LO_INV      (1.f / 1024.f)

// ---------------- helpers ----------------
__device__ __forceinline__ uint32_t s2u(const void* p) {
    uint32_t a;
    asm("{ .reg .u64 t; cvta.to.shared.u64 t, %1; cvt.u32.u64 %0, t; }" : "=r"(a) : "l"(p));
    return a;
}
// fp16 hi/lo split of two fp32 (f0 -> low half); lo scaled by LO_SCALE (subnormal fix)
__device__ __forceinline__ void split2s(float f0, float f1, uint32_t& hi, uint32_t& lo) {
    uint32_t h;
    asm("cvt.rn.f16x2.f32 %0, %1, %2;" : "=r"(h) : "f"(f1), "f"(f0));
    __half2 hh = *reinterpret_cast<__half2*>(&h);
    float l0 = (f0 - __low2float(hh)) * LO_SCALE;
    float l1 = (f1 - __high2float(hh)) * LO_SCALE;
    uint32_t l;
    asm("cvt.rn.f16x2.f32 %0, %1, %2;" : "=r"(l) : "f"(l1), "f"(l0));
    hi = h; lo = l;
}
__device__ __forceinline__ void ldm4(uint32_t a, uint32_t* r) {
    asm volatile("ldmatrix.sync.aligned.m8n8.x4.shared.b16 {%0,%1,%2,%3}, [%4];"
                 : "=r"(r[0]), "=r"(r[1]), "=r"(r[2]), "=r"(r[3]) : "r"(a));
}
__device__ __forceinline__ void mma_f32(float* c, const uint32_t* a, uint32_t b0, uint32_t b1) {
    asm volatile("mma.sync.aligned.m16n8k16.row.col.f32.f16.f16.f32 "
                 "{%0,%1,%2,%3}, {%4,%5,%6,%7}, {%8,%9}, {%0,%1,%2,%3};"
                 : "+f"(c[0]), "+f"(c[1]), "+f"(c[2]), "+f"(c[3])
                 : "r"(a[0]), "r"(a[1]), "r"(a[2]), "r"(a[3]), "r"(b0), "r"(b1));
}
__device__ __forceinline__ void mma_f16(uint32_t* c, const uint32_t* a, uint32_t b0, uint32_t b1) {
    asm volatile("mma.sync.aligned.m16n8k16.row.col.f16.f16.f16.f16 "
                 "{%0,%1}, {%2,%3,%4,%5}, {%6,%7}, {%0,%1};"
                 : "+r"(c[0]), "+r"(c[1])
                 : "r"(a[0]), "r"(a[1]), "r"(a[2]), "r"(a[3]), "r"(b0), "r"(b1));
}
__device__ __forceinline__ void cp16(uint32_t d, const void* s) {
    asm volatile("cp.async.cg.shared.global [%0], [%1], 16;" :: "r"(d), "l"(s));
}
__device__ __forceinline__ void cp_commit() { asm volatile("cp.async.commit_group;" ::: "memory"); }

// ---- F(4,3) weight transform core ----
__device__ __forceinline__ void wwcore(const float g[3][3], float U[6][6]) {
    const float i6 = 1.f / 6.f, i12 = 1.f / 12.f, i24 = 1.f / 24.f;
    float R[6][3];
#pragma unroll
    for (int c = 0; c < 3; c++) {
        R[0][c] = 0.25f * g[0][c];
        R[1][c] = -i6 * (g[0][c] + g[1][c] + g[2][c]);
        R[2][c] = i6 * (-g[0][c] + g[1][c] - g[2][c]);
        R[3][c] = i24 * g[0][c] + i12 * g[1][c] + i6 * g[2][c];
        R[4][c] = i24 * g[0][c] - i12 * g[1][c] + i6 * g[2][c];
        R[5][c] = g[2][c];
    }
#pragma unroll
    for (int r = 0; r < 6; r++) {
        U[r][0] = 0.25f * R[r][0];
        U[r][1] = -i6 * (R[r][0] + R[r][1] + R[r][2]);
        U[r][2] = i6 * (-R[r][0] + R[r][1] - R[r][2]);
        U[r][3] = i24 * R[r][0] + i12 * R[r][1] + i6 * R[r][2];
        U[r][4] = i24 * R[r][0] - i12 * R[r][1] + i6 * R[r][2];
        U[r][5] = R[r][2];
    }
}

// ---- all weight transforms in ONE launch: groups 0/1/2 = q/v/k, group 3 = out ----
__global__ void wino_w_all(const float* __restrict__ wq, const float* __restrict__ wv,
                           const float* __restrict__ wk, const float* __restrict__ wo,
                           __half* __restrict__ dq, __half* __restrict__ dv,
                           __half* __restrict__ dk,
                           __half* __restrict__ do0, __half* __restrict__ do1) {
    int grp = blockIdx.x >> 7;
    int t = (blockIdx.x & 127) * 256 + threadIdx.x;
    if (grp < 3) {
        const float* src = (grp == 0) ? wq : (grp == 1) ? wv : wk;
        __half* dst = (grp == 0) ? dq : (grp == 1) ? dv : dk;
        int ic = t & 255, oc = t >> 8;
        float g[3][3];
#pragma unroll
        for (int r = 0; r < 3; r++)
#pragma unroll
            for (int c = 0; c < 3; c++)
                g[r][c] = src[((long)oc * 256 + ic) * 9 + r * 3 + c];
        float U[6][6];
        wwcore(g, U);
#pragma unroll
        for (int comp = 0; comp < 36; comp++) {
            float x = U[comp / 6][comp % 6];
            __half hb = __float2half_rn(x);
            float lo = (x - __half2float(hb)) * LO_SCALE;
            long base = ((long)(comp * 8 + (ic >> 5)) * 128 + oc) * 64 + (ic & 31);
            dst[base] = hb;
            dst[base + 32] = __float2half_rn(lo);
        }
    } else {
        int ic = t & 127, oc = t >> 7;
        float g[3][3];
#pragma unroll
        for (int r = 0; r < 3; r++)
#pragma unroll
            for (int c = 0; c < 3; c++)
                g[r][c] = wo[((long)oc * 128 + ic) * 9 + r * 3 + c];
        float U[6][6];
        wwcore(g, U);
        __half* dst = (oc < 128) ? do0 : do1;
        int ocl = oc & 127;
#pragma unroll
        for (int comp = 0; comp < 36; comp++) {
            float x = U[comp / 6][comp % 6];
            __half hb = __float2half_rn(x);
            float lo = (x - __half2float(hb)) * LO_SCALE;
            long base = ((long)(comp * 4 + (ic >> 5)) * 128 + ocl) * 64 + (ic & 31);
            dst[base] = hb;
            dst[base + 32] = __float2half_rn(lo);
        }
    }
}

// ---- shared transform core: sm[32ch][6r][67] -> D[2][36] for (tx, j) ----
__device__ __forceinline__ void wtransform(const float* sm, int tx, int j, float D[2][36]) {
#pragma unroll
    for (int e = 0; e < 2; e++) {
        const float* s = sm + (2 * j + e) * 402 + 4 * tx;
        float T[6][6];
#pragma unroll
        for (int c = 0; c < 6; c++) {
            float x0 = s[c], x1 = s[67 + c], x2 = s[134 + c],
                  x3 = s[201 + c], x4 = s[268 + c], x5 = s[335 + c];
            T[0][c] = 4.f * x0 - 5.f * x2 + x4;
            T[1][c] = -4.f * x1 - 4.f * x2 + x3 + x4;
            T[2][c] = 4.f * x1 - 4.f * x2 - x3 + x4;
            T[3][c] = -2.f * x1 - x2 + 2.f * x3 + x4;
            T[4][c] = 2.f * x1 - x2 - 2.f * x3 + x4;
            T[5][c] = 4.f * x1 - 5.f * x3 + x5;
        }
#pragma unroll
        for (int r = 0; r < 6; r++) {
            float t0 = T[r][0], t1 = T[r][1], t2 = T[r][2],
                  t3 = T[r][3], t4 = T[r][4], t5 = T[r][5];
            D[e][r * 6 + 0] = 4.f * t0 - 5.f * t2 + t4;
            D[e][r * 6 + 1] = -4.f * t1 - 4.f * t2 + t3 + t4;
            D[e][r * 6 + 2] = 4.f * t1 - 4.f * t2 - t3 + t4;
            D[e][r * 6 + 3] = -2.f * t1 - t2 + 2.f * t3 + t4;
            D[e][r * 6 + 4] = 2.f * t1 - t2 - 2.f * t3 + t4;
            D[e][r * 6 + 5] = 4.f * t1 - 5.f * t3 + t5;
        }
    }
}

// ---- F(4,3) input transform: x (channel-major) -> xt; fBase = first frame ----
__global__ __launch_bounds__(256) void wino_in(const float* __restrict__ x, uint8_t* __restrict__ xt,
                                               int fBase) {
    extern __shared__ float sm[];   // [32 ch][6 rows][67]
    const int f = fBase + blockIdx.y, ty = blockIdx.x;
    const int t = threadIdx.x;
    const float* xf = x + (long)f * CHWX;
    const int gr0 = 4 * ty - 1;
    const int tx = t >> 4, j = t & 15;
    const long tileG = (long)f * 256 + ty * 16 + tx;

    for (int idx = t; idx < 32 * 6; idx += 256) {
        int r = idx % 6, ch = idx / 6;
        sm[(ch * 6 + r) * 67 + 0] = 0.f;
        sm[(ch * 6 + r) * 67 + 65] = 0.f;
    }

    for (int cc = 0; cc < 8; cc++) {
        __syncthreads();
        for (int idx = t; idx < 32 * 6 * 16; idx += 256) {
            int c4 = idx & 15, rc = idx >> 4;
            int r = rc % 6, ch = rc / 6;
            int gr = gr0 + r;
            float4 v = make_float4(0.f, 0.f, 0.f, 0.f);
            if ((unsigned)gr < 64u)
                v = *(const float4*)(xf + (long)(cc * 32 + ch) * HW + gr * 64 + c4 * 4);
            float* sp = sm + (ch * 6 + r) * 67 + 1 + c4 * 4;
            sp[0] = v.x; sp[1] = v.y; sp[2] = v.z; sp[3] = v.w;
        }
        __syncthreads();
        float D[2][36];
        wtransform(sm, tx, j, D);
        uint8_t* base = xt + tileG * 1024 + cc * 128 + j * 4;
#pragma unroll
        for (int comp = 0; comp < 36; comp++) {
            uint32_t h, l;
            split2s(D[0][comp], D[1][comp], h, l);
            uint32_t hN = __shfl_xor_sync(0xFFFFFFFFu, h, 1);
            uint32_t lN = __shfl_xor_sync(0xFFFFFFFFu, l, 1);
            if (!(j & 1)) {
                *(uint2*)(base + (long)comp * XT_PLANE_B) = make_uint2(h, hN);
                *(uint2*)(base + (long)comp * XT_PLANE_B + 64) = make_uint2(l, lN);
            }
        }
    }
}

// ---- F(4,3) input transform of pooled (pixel-major): gp -> xtp ----
__global__ __launch_bounds__(256) void wino_in_p(const float* __restrict__ gp, uint8_t* __restrict__ xtp) {
    extern __shared__ float sm[];
    const int b = blockIdx.y, ty = blockIdx.x;
    const int t = threadIdx.x;
    const float* gb = gp + (long)b * HW * 128;
    const int gr0 = 4 * ty - 1;
    const int tx = t >> 4, j = t & 15;
    const long tileG = (long)b * 256 + ty * 16 + tx;

    for (int idx = t; idx < 32 * 6; idx += 256) {
        int r = idx % 6, ch = idx / 6;
        sm[(ch * 6 + r) * 67 + 0] = 0.f;
        sm[(ch * 6 + r) * 67 + 65] = 0.f;
    }

    for (int cc = 0; cc < 4; cc++) {
        __syncthreads();
        for (int idx = t; idx < 6 * 64 * 8; idx += 256) {
            int ch4 = idx & 7, pc = idx >> 3;
            int gc = pc & 63, r = pc >> 6;
            int gr = gr0 + r;
            float4 v = make_float4(0.f, 0.f, 0.f, 0.f);
            if ((unsigned)gr < 64u)
                v = *(const float4*)(gb + (long)(gr * 64 + gc) * 128 + cc * 32 + ch4 * 4);
            int ch = ch4 * 4;
            sm[((ch + 0) * 6 + r) * 67 + 1 + gc] = v.x;
            sm[((ch + 1) * 6 + r) * 67 + 1 + gc] = v.y;
            sm[((ch + 2) * 6 + r) * 67 + 1 + gc] = v.z;
            sm[((ch + 3) * 6 + r) * 67 + 1 + gc] = v.w;
        }
        __syncthreads();
        float D[2][36];
        wtransform(sm, tx, j, D);
        uint8_t* base = xtp + tileG * 512 + cc * 128 + j * 4;
#pragma unroll
        for (int comp = 0; comp < 36; comp++) {
            uint32_t h, l;
            split2s(D[0][comp], D[1][comp], h, l);
            uint32_t hN = __shfl_xor_sync(0xFFFFFFFFu, h, 1);
            uint32_t lN = __shfl_xor_sync(0xFFFFFFFFu, l, 1);
            if (!(j & 1)) {
                *(uint2*)(base + (long)comp * XTP_PLANE_B) = make_uint2(h, hN);
                *(uint2*)(base + (long)comp * XTP_PLANE_B + 64) = make_uint2(l, lN);
            }
        }
    }
}

// ---------------- persistent Winograd GEMM (fp16 split; f32 hi*hi + f16 scaled cross) ----------------
// MAP 0 (per-half): qv items [0,nQV): comp=item>>5, 32 blocks of frames [half*16, half*16+16);
//                   k items [nQV,nItems): 4 blocks (key frames half*16+{0,8}).
// MAP 2: out conv (8 blocks/comp).
template <int NW, int KITERS, int MAP>
__global__ __launch_bounds__(256) void wino_gemm_p(
    const uint8_t* __restrict__ xt, long xtPlaneB,
    const __half* __restrict__ wt0, const __half* __restrict__ wt1,
    const __half* __restrict__ wtk, float* __restrict__ ytk,
    float* __restrict__ yt0, float* __restrict__ yt1,
    int nItems, int nQV, long ytPlane, int half)
{
    constexpr int STAGE = 16384 * (1 + NW);
    extern __shared__ __align__(16) char dsm[];
    const uint32_t sb = s2u(dsm);
    const int t = threadIdx.x, lane = t & 31, w = t >> 5;
    const int wm = w >> 2, wn = w & 3;
    const int fp = t >> 1, fsub = (t & 1) * 4;

    const int nloc = (nItems - blockIdx.x + gridDim.x - 1) / gridDim.x;
    if (nloc <= 0) return;
    const int totalP = nloc * KITERS;

    auto issue = [&](int p) {
        const int j = p / KITERS, it = p % KITERS;
        const int item = blockIdx.x + j * (int)gridDim.x;
        int comp; long tileB0; bool kit = false;
        const __half* wA0 = wt0;
        if (MAP == 0) {
            if (item < nQV) { comp = item >> 5; tileB0 = (long)half * 4096 + (item & 31) * 128; }
            else {
                int i2 = item - nQV; comp = i2 >> 2; int r = i2 & 3;
                tileB0 = (long)half * 4096 + (r >> 1) * 2048 + (r & 1) * 128;
                kit = true; wA0 = wtk;
            }
        } else { comp = item >> 3; tileB0 = (long)(item & 7) * 128; }
        const uint32_t bufB = sb + (p & 3) * STAGE;
        const uint32_t bufA = bufB + 16384;
        const uint8_t* srcB = xt + (long)comp * xtPlaneB + ((tileB0 + fp) * KITERS + it) * 128;
#pragma unroll
        for (int i = 0; i < 4; i++) {
            int q = fsub + i;
            cp16(bufB + fp * 128 + ((q ^ (fp & 7)) << 4), srcB + q * 16);
        }
        const long aoff = ((long)(comp * KITERS + it) * 128 + fp) * 64;
#pragma unroll
        for (int s = 0; s < NW; s++) {
            if (s == 1 && kit) break;
            const uint8_t* srcA = (const uint8_t*)((s ? wt1 : wA0) + aoff);
#pragma unroll
            for (int i = 0; i < 4; i++) {
                int q = fsub + i;
                cp16(bufA + s * 16384 + fp * 128 + ((q ^ (fp & 7)) << 4), srcA + q * 16);
            }
        }
    };

    float acc[NW][4][4][4];
    uint32_t acch[NW][4][4][2];
#pragma unroll
    for (int s = 0; s < NW; s++)
#pragma unroll
        for (int i = 0; i < 4; i++)
#pragma unroll
            for (int jj = 0; jj < 4; jj++) {
#pragma unroll
                for (int r = 0; r < 4; r++) acc[s][i][jj][r] = 0.f;
                acch[s][i][jj][0] = 0u; acch[s][i][jj][1] = 0u;
            }

#pragma unroll
    for (int p = 0; p < 3; p++) { issue(p); cp_commit(); }

    for (int j = 0; j < nloc; j++) {
        const int item = blockIdx.x + j * (int)gridDim.x;
        const bool kit = (MAP == 0) && (item >= nQV);
        for (int it = 0; it < KITERS; it++) {
            const int p = j * KITERS + it;
            asm volatile("cp.async.wait_group 2;" ::: "memory");
            __syncthreads();
            const uint32_t bufB = sb + (p & 3) * STAGE;
            const uint32_t bufA = bufB + 16384;
#pragma unroll
            for (int ks = 0; ks < 2; ks++) {
                uint32_t Bh[2][4], Bl[2][4];
#pragma unroll
                for (int g = 0; g < 2; g++) {
                    int pp = wn * 32 + g * 16 + (lane & 15);
                    uint32_t rb = bufB + pp * 128;
                    int p7 = pp & 7, qh = ks * 2 + (lane >> 4);
                    ldm4(rb + ((qh ^ p7) << 4), Bh[g]);
                    ldm4(rb + (((qh + 4) ^ p7) << 4), Bl[g]);
                }
#pragma unroll
                for (int s = 0; s < NW; s++) {
                    if (s == 1 && kit) break;
#pragma unroll
                    for (int i = 0; i < 4; i++) {
                        int r = wm * 64 + i * 16 + (lane & 15);
                        uint32_t ra = bufA + s * 16384 + r * 128;
                        int r7 = r & 7, qh = ks * 2 + (lane >> 4);
                        uint32_t Ah[4], Al[4];
                        ldm4(ra + ((qh ^ r7) << 4), Ah);
                        ldm4(ra + (((qh + 4) ^ r7) << 4), Al);
#pragma unroll
                        for (int jj = 0; jj < 4; jj++) {
                            int g = jj >> 1, rs = jj & 1;
                            mma_f32(acc[s][i][jj], Ah, Bh[g][rs], Bh[g][rs + 2]);
                            mma_f16(acch[s][i][jj], Ah, Bl[g][rs], Bl[g][rs + 2]);
                            mma_f16(acch[s][i][jj], Al, Bh[g][rs], Bh[g][rs + 2]);
                        }
                    }
                }
            }
            if (p + 3 < totalP) issue(p + 3);
            cp_commit();
        }

        // ---- epilogue (buffer 3 free for staging); cross terms scaled back by LO_INV ----
        {
            int comp; long ytTile0;
            float* dst0 = yt0; float* dst1 = yt1; long plane = ytPlane;
            if (MAP == 0 && kit) {
                int i2 = item - nQV; comp = i2 >> 2; int r = i2 & 3;
                ytTile0 = (long)half * 512 + (r >> 1) * 256 + (r & 1) * 128;
                dst0 = ytk; plane = YTK_PLANE;
            } else if (MAP == 0) { comp = item >> 5; ytTile0 = (long)half * 4096 + (item & 31) * 128; }
            else { comp = item >> 3; ytTile0 = (long)(item & 7) * 128; }
            float* stage = (float*)(dsm + 3 * STAGE);
#pragma unroll
            for (int s = 0; s < NW; s++) {
                if (s == 1 && kit) break;
                float* ytS = (s ? dst1 : dst0) + (long)comp * plane + ytTile0 * 128;
#pragma unroll
                for (int pass = 0; pass < 4; pass++) {
                    __syncthreads();
                    if (wn == pass) {
#pragma unroll
                        for (int i = 0; i < 4; i++) {
                            int m = wm * 64 + i * 16 + (lane >> 2);
#pragma unroll
                            for (int jj = 0; jj < 4; jj++) {
                                int nn = jj * 8 + (lane & 3) * 2;
                                __half2 c01 = *(__half2*)&acch[s][i][jj][0];
                                __half2 c23 = *(__half2*)&acch[s][i][jj][1];
                                stage[nn * 132 + m]           = acc[s][i][jj][0] + __low2float(c01) * LO_INV;
                                stage[(nn + 1) * 132 + m]     = acc[s][i][jj][1] + __high2float(c01) * LO_INV;
                                stage[nn * 132 + m + 8]       = acc[s][i][jj][2] + __low2float(c23) * LO_INV;
                                stage[(nn + 1) * 132 + m + 8] = acc[s][i][jj][3] + __high2float(c23) * LO_INV;
                            }
                        }
                    }
                    __syncthreads();
#pragma unroll
                    for (int kk = 0; kk < 4; kk++) {
                        int idx = t + kk * 256;
                        int r = idx >> 5, q = idx & 31;
                        *(float4*)(ytS + (long)(pass * 32 + r) * 128 + q * 4) =
                            *(float4*)(stage + r * 132 + q * 4);
                    }
                }
            }
            __syncthreads();
#pragma unroll
            for (int s = 0; s < NW; s++)
#pragma unroll
                for (int i = 0; i < 4; i++)
#pragma unroll
                    for (int jj = 0; jj < 4; jj++) {
#pragma unroll
                        for (int r = 0; r < 4; r++) acc[s][i][jj][r] = 0.f;
                        acch[s][i][jj][0] = 0u; acch[s][i][jj][1] = 0u;
                    }
        }
    }
}

// ---- F(4,3) inverse transform of 36 comps -> 16 pixels (register-resident) ----
__device__ __forceinline__ void inv36(const float* __restrict__ Y, long plane, float* o) {
    float y[36];
#pragma unroll
    for (int c = 0; c < 36; c++) y[c] = __ldg(Y + c * plane);
    float Z[4][6];
#pragma unroll
    for (int c = 0; c < 6; c++) {
        float a0 = y[c], a1 = y[6 + c], a2 = y[12 + c],
              a3 = y[18 + c], a4 = y[24 + c], a5 = y[30 + c];
        Z[0][c] = a0 + a1 + a2 + a3 + a4;
        Z[1][c] = a1 - a2 + 2.f * a3 - 2.f * a4;
        Z[2][c] = a1 + a2 + 4.f * a3 + 4.f * a4;
        Z[3][c] = a1 - a2 + 8.f * a3 - 8.f * a4 + a5;
    }
#pragma unroll
    for (int a = 0; a < 4; a++) {
        float z0 = Z[a][0], z1 = Z[a][1], z2 = Z[a][2],
              z3 = Z[a][3], z4 = Z[a][4], z5 = Z[a][5];
        o[a * 4 + 0] = z0 + z1 + z2 + z3 + z4;
        o[a * 4 + 1] = z1 - z2 + 2.f * z3 - 2.f * z4;
        o[a * 4 + 2] = z1 + z2 + 4.f * z3 + 4.f * z4;
        o[a * 4 + 3] = z1 - z2 + 8.f * z3 - 8.f * z4 + z5;
    }
}

// ---- fused inverse-transform + attention -> pooled fp32 pixel-major ----
__global__ __launch_bounds__(256) void attn_wino(
    const float* __restrict__ yt, const float* __restrict__ ytk,
    float* __restrict__ gp)
{
    __shared__ float sdots[2][4][16];
    __shared__ float fdots[2][16];
    __shared__ float stage[2][16][128];
    const int t = threadIdx.x, lane = t & 31;
    const int oc = t & 127, tl = t >> 7;
    const int wsub = (t >> 5) & 3;
    const int b = blockIdx.x >> 7, tp = blockIdx.x & 127;
    const int tloc = tp * 2 + tl;

    float k16[16];
    inv36(ytk + (long)(b * 256 + tloc) * 128 + oc, YTK_PLANE, k16);

    float m[16], s[16], acc[16];

    for (int f = 0; f < 8; f++) {
        const long tg = ((long)((b * 8 + f) * 256 + tloc)) * 128 + oc;
        float q16[16];
        inv36(yt + tg, YT_PLANE, q16);
        float p[16];
#pragma unroll
        for (int px = 0; px < 16; px++) p[px] = q16[px] * k16[px];
#pragma unroll
        for (int off = 16; off; off >>= 1)
#pragma unroll
            for (int px = 0; px < 16; px++) p[px] += __shfl_xor_sync(0xFFFFFFFFu, p[px], off);
        if (lane == 0)
#pragma unroll
            for (int px = 0; px < 16; px++) sdots[tl][wsub][px] = p[px];
        __syncthreads();
        if (t < 32) {
            int t2 = t >> 4, px = t & 15;
            fdots[t2][px] = sdots[t2][0][px] + sdots[t2][1][px] + sdots[t2][2][px] + sdots[t2][3][px];
        }
        float v16[16];
        inv36(yt + YT_SET + tg, YT_PLANE, v16);
        __syncthreads();
#pragma unroll
        for (int px = 0; px < 16; px++) {
            float d = fdots[tl][px];
            if (f == 0) { m[px] = d; s[px] = 1.f; acc[px] = v16[px]; }
            else {
                float nm = fmaxf(m[px], d);
                float sc = expf(m[px] - nm);
                float e  = expf(d - nm);
                s[px] = s[px] * sc + e;
                acc[px] = acc[px] * sc + e * v16[px];
                m[px] = nm;
            }
        }
    }

#pragma unroll
    for (int px = 0; px < 16; px++) stage[tl][px][oc] = acc[px] / s[px];
    __syncthreads();
    for (int idx = t; idx < 2 * 16 * 32; idx += 256) {
        int l = idx & 31, px = (idx >> 5) & 15, tt = idx >> 9;
        int tw = tp * 2 + tt;
        int ty = tw >> 4, tx = tw & 15;
        int pix = (4 * ty + (px >> 2)) * 64 + 4 * tx + (px & 3);
        float4 v = *(float4*)&stage[tt][px][l * 4];
        *(float4*)(gp + ((long)(b * HW + pix)) * 128 + l * 4) = v;
    }
}

// ---- final: inverse transform + bias + T-broadcast, full-row staged stores ----
__global__ __launch_bounds__(256) void wino_out_final(
    const float* __restrict__ yto, const float* __restrict__ bias, float* __restrict__ out)
{
    extern __shared__ float st[];   // [4 rows][64 cols][128 oc] = 128KB
    const int b = blockIdx.x >> 5, rest = blockIdx.x & 31;
    const int ty = rest >> 1, half = rest & 1;
    const int t = threadIdx.x;
    const int oc = t & 127, tl = t >> 7;

    for (int pass = 0; pass < 8; pass++) {
        int tx = pass * 2 + tl;
        long tile = (long)b * 256 + ty * 16 + tx;
        const float* Y = yto + (long)half * YTO_HALF + tile * 128 + oc;
        float o[16];
        inv36(Y, YTO_PLANE, o);
#pragma unroll
        for (int px = 0; px < 16; px++)
            st[((px >> 2) * 64 + tx * 4 + (px & 3)) * 128 + oc] = o[px];
    }
    __syncthreads();

    for (int u = t; u < 512; u += 256) {
        int oc2 = u & 127, row = u >> 7;
        float bv = bias[half * 128 + oc2];
        float4 rv[16];
#pragma unroll
        for (int c4 = 0; c4 < 16; c4++) {
            rv[c4].x = st[(row * 64 + c4 * 4 + 0) * 128 + oc2] + bv;
            rv[c4].y = st[(row * 64 + c4 * 4 + 1) * 128 + oc2] + bv;
            rv[c4].z = st[(row * 64 + c4 * 4 + 2) * 128 + oc2] + bv;
            rv[c4].w = st[(row * 64 + c4 * 4 + 3) * 128 + oc2] + bv;
        }
#pragma unroll
        for (int tt = 0; tt < 8; tt++) {
            float* op = out + ((long)(b * 8 + tt) * 256 + half * 128 + oc2) * HW
                        + (ty * 4 + row) * 64;
#pragma unroll
            for (int c4 = 0; c4 < 16; c4++)
                *(float4*)(op + c4 * 4) = rv[c4];
        }
    }
}

// ---------------------------------------------------------------------------
extern "C" void kernel_launch(void* const* d_in, const int* in_sizes, int n_in,
                              void* d_out, int out_size)
{
    const float* x     = (const float*)d_in[0];
    const float* w_k   = (const float*)d_in[1];
    const float* w_q   = (const float*)d_in[2];
    const float* w_v   = (const float*)d_in[3];
    const float* w_out = (const float*)d_in[4];
    const float* b_out = (const float*)d_in[5];
    float* out = (float*)d_out;

    void* basev = nullptr;
    cudaGetSymbolAddress(&basev, g_scratch);
    float* S = (float*)basev;
    float* gp = S + OFF_GP;
    __half* wtO0 = (__half*)(S + OFF_WTO0);
    __half* wtO1 = (__half*)(S + OFF_WTO1);
    __half* wtq  = (__half*)(S + OFF_WTQ);
    __half* wtv  = (__half*)(S + OFF_WTV);
    __half* wtk  = (__half*)(S + OFF_WTK);
    uint8_t* xtp = (uint8_t*)(S + OFF_XTP);
    float*   yto = S + OFF_YTO;
    uint8_t* xt  = (uint8_t*)(S + OFF_XT);
    float*   yt  = S + OFF_YT;
    float*   ytk = S + OFF_YTK;

    const int DSM2 = 4 * 49152;
    const int DSMW = 32 * 6 * 67 * 4;
    const int DSMF = 4 * 64 * 128 * 4;

    static bool inited = false;
    static cudaStream_t s2;
    static cudaEvent_t ev0, ev1, ev2, ev3;
    if (!inited) {
        cudaFuncSetAttribute(wino_gemm_p<2, 8, 0>, cudaFuncAttributeMaxDynamicSharedMemorySize, DSM2);
        cudaFuncSetAttribute(wino_gemm_p<2, 4, 2>, cudaFuncAttributeMaxDynamicSharedMemorySize, DSM2);
        cudaFuncSetAttribute(wino_in,   cudaFuncAttributeMaxDynamicSharedMemorySize, DSMW);
        cudaFuncSetAttribute(wino_in_p, cudaFuncAttributeMaxDynamicSharedMemorySize, DSMW);
        cudaFuncSetAttribute(wino_out_final, cudaFuncAttributeMaxDynamicSharedMemorySize, DSMF);
        cudaStreamCreateWithFlags(&s2, cudaStreamNonBlocking);
        cudaEventCreateWithFlags(&ev0, cudaEventDisableTiming);
        cudaEventCreateWithFlags(&ev1, cudaEventDisableTiming);
        cudaEventCreateWithFlags(&ev2, cudaEventDisableTiming);
        cudaEventCreateWithFlags(&ev3, cudaEventDisableTiming);
        inited = true;
    }

    // fork s2 off the capture stream; weight transforms run concurrently with wino_in half-1
    cudaEventRecord(ev0, 0);
    cudaStreamWaitEvent(s2, ev0, 0);
    wino_w_all<<<512, 256, 0, s2>>>(w_q, w_v, w_k, w_out, wtq, wtv, wtk, wtO0, wtO1);

    wino_in<<<dim3(16, 16), 256, DSMW, 0>>>(x, xt, 0);     // frames 0-15
    cudaEventRecord(ev1, 0);
    wino_in<<<dim3(16, 16), 256, DSMW, 0>>>(x, xt, 16);    // frames 16-31
    cudaEventRecord(ev2, 0);

    // GEMM half-1 (frames 0-15 + key frames 0,8) overlaps wino_in half-2
    cudaStreamWaitEvent(s2, ev1, 0);
    wino_gemm_p<2, 8, 0><<<148, 256, DSM2, s2>>>(
        xt, XT_PLANE_B, wtq, wtv, wtk, ytk, yt, yt + YT_SET, 1296, 1152, YT_PLANE, 0);
    cudaStreamWaitEvent(s2, ev2, 0);
    wino_gemm_p<2, 8, 0><<<148, 256, DSM2, s2>>>(
        xt, XT_PLANE_B, wtq, wtv, wtk, ytk, yt, yt + YT_SET, 1296, 1152, YT_PLANE, 1);
    cudaEventRecord(ev3, s2);
    cudaStreamWaitEvent(0, ev3, 0);

    // fused inverse transform + attention -> pooled fp32 pixel-major
    attn_wino<<<512, 256, 0, 0>>>(yt, ytk, gp);

    // out conv via Winograd
    wino_in_p<<<dim3(16, 4), 256, DSMW, 0>>>(gp, xtp);
    wino_gemm_p<2, 4, 2><<<148, 256, DSM2, 0>>>(
        xtp, XTP_PLANE_B, wtO0, wtO1, nullptr, nullptr, yto, yto + YTO_HALF, 288, 288, YTO_PLANE, 0);
    wino_out_final<<<128, 256, DSMF, 0>>>(yto, b_out, out);
}

// round 14
// speedup vs baseline: 1.1078x; 1.1078x over previous
#include <cuda_runtime.h>
#include <cuda_fp16.h>
#include <cstdint>

#define HW 4096
#define CHWX ((long)256 * HW)

// float offsets in g_scratch
#define OFF_GP    35651584L
#define OFF_WTO0  37748736L
#define OFF_WTO1  38338560L
#define OFF_WTQ   38928384L
#define OFF_WTV   40108032L
#define OFF_WTK   41287680L
#define OFF_XTP   42467328L
#define OFF_YTO   47185920L
#define OFF_XT    56623104L
#define OFF_YT    132120576L
#define OFF_YTK   207618048L
__device__ __align__(256) float g_scratch[212336640];

#define XT_PLANE_B  8388608L
#define XTP_PLANE_B 524288L
#define YT_PLANE    1048576L
#define YT_SET      37748736L
#define YTK_PLANE   131072L
#define YTO_PLANE   131072L
#define YTO_HALF    4718592L

#define LO_SCALE    1024.f
#define LO_INV      (1.f / 1024.f)

// ---------------- helpers ----------------
__device__ __forceinline__ uint32_t s2u(const void* p) {
    uint32_t a;
    asm("{ .reg .u64 t; cvta.to.shared.u64 t, %1; cvt.u32.u64 %0, t; }" : "=r"(a) : "l"(p));
    return a;
}
// fp16 hi/lo split of two fp32 (f0 -> low half); lo scaled by LO_SCALE (subnormal fix)
__device__ __forceinline__ void split2s(float f0, float f1, uint32_t& hi, uint32_t& lo) {
    uint32_t h;
    asm("cvt.rn.f16x2.f32 %0, %1, %2;" : "=r"(h) : "f"(f1), "f"(f0));
    __half2 hh = *reinterpret_cast<__half2*>(&h);
    float l0 = (f0 - __low2float(hh)) * LO_SCALE;
    float l1 = (f1 - __high2float(hh)) * LO_SCALE;
    uint32_t l;
    asm("cvt.rn.f16x2.f32 %0, %1, %2;" : "=r"(l) : "f"(l1), "f"(l0));
    hi = h; lo = l;
}
__device__ __forceinline__ void ldm4(uint32_t a, uint32_t* r) {
    asm volatile("ldmatrix.sync.aligned.m8n8.x4.shared.b16 {%0,%1,%2,%3}, [%4];"
                 : "=r"(r[0]), "=r"(r[1]), "=r"(r[2]), "=r"(r[3]) : "r"(a));
}
__device__ __forceinline__ void mma_f32(float* c, const uint32_t* a, uint32_t b0, uint32_t b1) {
    asm volatile("mma.sync.aligned.m16n8k16.row.col.f32.f16.f16.f32 "
                 "{%0,%1,%2,%3}, {%4,%5,%6,%7}, {%8,%9}, {%0,%1,%2,%3};"
                 : "+f"(c[0]), "+f"(c[1]), "+f"(c[2]), "+f"(c[3])
                 : "r"(a[0]), "r"(a[1]), "r"(a[2]), "r"(a[3]), "r"(b0), "r"(b1));
}
__device__ __forceinline__ void mma_f16(uint32_t* c, const uint32_t* a, uint32_t b0, uint32_t b1) {
    asm volatile("mma.sync.aligned.m16n8k16.row.col.f16.f16.f16.f16 "
                 "{%0,%1}, {%2,%3,%4,%5}, {%6,%7}, {%0,%1};"
                 : "+r"(c[0]), "+r"(c[1])
                 : "r"(a[0]), "r"(a[1]), "r"(a[2]), "r"(a[3]), "r"(b0), "r"(b1));
}
__device__ __forceinline__ void cp16(uint32_t d, const void* s) {
    asm volatile("cp.async.cg.shared.global [%0], [%1], 16;" :: "r"(d), "l"(s));
}
__device__ __forceinline__ void cp_commit() { asm volatile("cp.async.commit_group;" ::: "memory"); }

// ---- F(4,3) weight transform core ----
__device__ __forceinline__ void wwcore(const float g[3][3], float U[6][6]) {
    const float i6 = 1.f / 6.f, i12 = 1.f / 12.f, i24 = 1.f / 24.f;
    float R[6][3];
#pragma unroll
    for (int c = 0; c < 3; c++) {
        R[0][c] = 0.25f * g[0][c];
        R[1][c] = -i6 * (g[0][c] + g[1][c] + g[2][c]);
        R[2][c] = i6 * (-g[0][c] + g[1][c] - g[2][c]);
        R[3][c] = i24 * g[0][c] + i12 * g[1][c] + i6 * g[2][c];
        R[4][c] = i24 * g[0][c] - i12 * g[1][c] + i6 * g[2][c];
        R[5][c] = g[2][c];
    }
#pragma unroll
    for (int r = 0; r < 6; r++) {
        U[r][0] = 0.25f * R[r][0];
        U[r][1] = -i6 * (R[r][0] + R[r][1] + R[r][2]);
        U[r][2] = i6 * (-R[r][0] + R[r][1] - R[r][2]);
        U[r][3] = i24 * R[r][0] + i12 * R[r][1] + i6 * R[r][2];
        U[r][4] = i24 * R[r][0] - i12 * R[r][1] + i6 * R[r][2];
        U[r][5] = R[r][2];
    }
}

// ---- all weight transforms in ONE launch: groups 0/1/2 = q/v/k, group 3 = out ----
__global__ void wino_w_all(const float* __restrict__ wq, const float* __restrict__ wv,
                           const float* __restrict__ wk, const float* __restrict__ wo,
                           __half* __restrict__ dq, __half* __restrict__ dv,
                           __half* __restrict__ dk,
                           __half* __restrict__ do0, __half* __restrict__ do1) {
    int grp = blockIdx.x >> 7;
    int t = (blockIdx.x & 127) * 256 + threadIdx.x;
    if (grp < 3) {
        const float* src = (grp == 0) ? wq : (grp == 1) ? wv : wk;
        __half* dst = (grp == 0) ? dq : (grp == 1) ? dv : dk;
        int ic = t & 255, oc = t >> 8;
        float g[3][3];
#pragma unroll
        for (int r = 0; r < 3; r++)
#pragma unroll
            for (int c = 0; c < 3; c++)
                g[r][c] = src[((long)oc * 256 + ic) * 9 + r * 3 + c];
        float U[6][6];
        wwcore(g, U);
#pragma unroll
        for (int comp = 0; comp < 36; comp++) {
            float x = U[comp / 6][comp % 6];
            __half hb = __float2half_rn(x);
            float lo = (x - __half2float(hb)) * LO_SCALE;
            long base = ((long)(comp * 8 + (ic >> 5)) * 128 + oc) * 64 + (ic & 31);
            dst[base] = hb;
            dst[base + 32] = __float2half_rn(lo);
        }
    } else {
        int ic = t & 127, oc = t >> 7;
        float g[3][3];
#pragma unroll
        for (int r = 0; r < 3; r++)
#pragma unroll
            for (int c = 0; c < 3; c++)
                g[r][c] = wo[((long)oc * 128 + ic) * 9 + r * 3 + c];
        float U[6][6];
        wwcore(g, U);
        __half* dst = (oc < 128) ? do0 : do1;
        int ocl = oc & 127;
#pragma unroll
        for (int comp = 0; comp < 36; comp++) {
            float x = U[comp / 6][comp % 6];
            __half hb = __float2half_rn(x);
            float lo = (x - __half2float(hb)) * LO_SCALE;
            long base = ((long)(comp * 4 + (ic >> 5)) * 128 + ocl) * 64 + (ic & 31);
            dst[base] = hb;
            dst[base + 32] = __float2half_rn(lo);
        }
    }
}

// ---- shared transform core: sm[32ch][6r][67] -> D[2][36] for (tx, j) ----
__device__ __forceinline__ void wtransform(const float* sm, int tx, int j, float D[2][36]) {
#pragma unroll
    for (int e = 0; e < 2; e++) {
        const float* s = sm + (2 * j + e) * 402 + 4 * tx;
        float T[6][6];
#pragma unroll
        for (int c = 0; c < 6; c++) {
            float x0 = s[c], x1 = s[67 + c], x2 = s[134 + c],
                  x3 = s[201 + c], x4 = s[268 + c], x5 = s[335 + c];
            T[0][c] = 4.f * x0 - 5.f * x2 + x4;
            T[1][c] = -4.f * x1 - 4.f * x2 + x3 + x4;
            T[2][c] = 4.f * x1 - 4.f * x2 - x3 + x4;
            T[3][c] = -2.f * x1 - x2 + 2.f * x3 + x4;
            T[4][c] = 2.f * x1 - x2 - 2.f * x3 + x4;
            T[5][c] = 4.f * x1 - 5.f * x3 + x5;
        }
#pragma unroll
        for (int r = 0; r < 6; r++) {
            float t0 = T[r][0], t1 = T[r][1], t2 = T[r][2],
                  t3 = T[r][3], t4 = T[r][4], t5 = T[r][5];
            D[e][r * 6 + 0] = 4.f * t0 - 5.f * t2 + t4;
            D[e][r * 6 + 1] = -4.f * t1 - 4.f * t2 + t3 + t4;
            D[e][r * 6 + 2] = 4.f * t1 - 4.f * t2 - t3 + t4;
            D[e][r * 6 + 3] = -2.f * t1 - t2 + 2.f * t3 + t4;
            D[e][r * 6 + 4] = 2.f * t1 - t2 - 2.f * t3 + t4;
            D[e][r * 6 + 5] = 4.f * t1 - 5.f * t3 + t5;
        }
    }
}

// ---- F(4,3) input transform: x (channel-major) -> xt ----
__global__ __launch_bounds__(256) void wino_in(const float* __restrict__ x, uint8_t* __restrict__ xt) {
    extern __shared__ float sm[];   // [32 ch][6 rows][67]
    const int f = blockIdx.y, ty = blockIdx.x;
    const int t = threadIdx.x;
    const float* xf = x + (long)f * CHWX;
    const int gr0 = 4 * ty - 1;
    const int tx = t >> 4, j = t & 15;
    const long tileG = (long)f * 256 + ty * 16 + tx;

    for (int idx = t; idx < 32 * 6; idx += 256) {
        int r = idx % 6, ch = idx / 6;
        sm[(ch * 6 + r) * 67 + 0] = 0.f;
        sm[(ch * 6 + r) * 67 + 65] = 0.f;
    }

    for (int cc = 0; cc < 8; cc++) {
        __syncthreads();
        for (int idx = t; idx < 32 * 6 * 16; idx += 256) {
            int c4 = idx & 15, rc = idx >> 4;
            int r = rc % 6, ch = rc / 6;
            int gr = gr0 + r;
            float4 v = make_float4(0.f, 0.f, 0.f, 0.f);
            if ((unsigned)gr < 64u)
                v = *(const float4*)(xf + (long)(cc * 32 + ch) * HW + gr * 64 + c4 * 4);
            float* sp = sm + (ch * 6 + r) * 67 + 1 + c4 * 4;
            sp[0] = v.x; sp[1] = v.y; sp[2] = v.z; sp[3] = v.w;
        }
        __syncthreads();
        float D[2][36];
        wtransform(sm, tx, j, D);
        uint8_t* base = xt + tileG * 1024 + cc * 128 + j * 4;
#pragma unroll
        for (int comp = 0; comp < 36; comp++) {
            uint32_t h, l;
            split2s(D[0][comp], D[1][comp], h, l);
            uint32_t hN = __shfl_xor_sync(0xFFFFFFFFu, h, 1);
            uint32_t lN = __shfl_xor_sync(0xFFFFFFFFu, l, 1);
            if (!(j & 1)) {
                *(uint2*)(base + (long)comp * XT_PLANE_B) = make_uint2(h, hN);
                *(uint2*)(base + (long)comp * XT_PLANE_B + 64) = make_uint2(l, lN);
            }
        }
    }
}

// ---- F(4,3) input transform of pooled (pixel-major): gp -> xtp ----
__global__ __launch_bounds__(256) void wino_in_p(const float* __restrict__ gp, uint8_t* __restrict__ xtp) {
    extern __shared__ float sm[];
    const int b = blockIdx.y, ty = blockIdx.x;
    const int t = threadIdx.x;
    const float* gb = gp + (long)b * HW * 128;
    const int gr0 = 4 * ty - 1;
    const int tx = t >> 4, j = t & 15;
    const long tileG = (long)b * 256 + ty * 16 + tx;

    for (int idx = t; idx < 32 * 6; idx += 256) {
        int r = idx % 6, ch = idx / 6;
        sm[(ch * 6 + r) * 67 + 0] = 0.f;
        sm[(ch * 6 + r) * 67 + 65] = 0.f;
    }

    for (int cc = 0; cc < 4; cc++) {
        __syncthreads();
        for (int idx = t; idx < 6 * 64 * 8; idx += 256) {
            int ch4 = idx & 7, pc = idx >> 3;
            int gc = pc & 63, r = pc >> 6;
            int gr = gr0 + r;
            float4 v = make_float4(0.f, 0.f, 0.f, 0.f);
            if ((unsigned)gr < 64u)
                v = *(const float4*)(gb + (long)(gr * 64 + gc) * 128 + cc * 32 + ch4 * 4);
            int ch = ch4 * 4;
            sm[((ch + 0) * 6 + r) * 67 + 1 + gc] = v.x;
            sm[((ch + 1) * 6 + r) * 67 + 1 + gc] = v.y;
            sm[((ch + 2) * 6 + r) * 67 + 1 + gc] = v.z;
            sm[((ch + 3) * 6 + r) * 67 + 1 + gc] = v.w;
        }
        __syncthreads();
        float D[2][36];
        wtransform(sm, tx, j, D);
        uint8_t* base = xtp + tileG * 512 + cc * 128 + j * 4;
#pragma unroll
        for (int comp = 0; comp < 36; comp++) {
            uint32_t h, l;
            split2s(D[0][comp], D[1][comp], h, l);
            uint32_t hN = __shfl_xor_sync(0xFFFFFFFFu, h, 1);
            uint32_t lN = __shfl_xor_sync(0xFFFFFFFFu, l, 1);
            if (!(j & 1)) {
                *(uint2*)(base + (long)comp * XTP_PLANE_B) = make_uint2(h, hN);
                *(uint2*)(base + (long)comp * XTP_PLANE_B + 64) = make_uint2(l, lN);
            }
        }
    }
}

// ---------------- persistent Winograd GEMM, 512 threads / 16 warps ----------------
// Warp grid 4m x 4n; per-warp tile 32(M) x 32(N). fp16 split: f32 hi*hi + f16 scaled cross.
// MAP 0: qv items [0,nQV) + merged k items [nQV,nItems). MAP 2: out conv.
template <int NW, int KITERS, int MAP>
__global__ __launch_bounds__(512, 1) void wino_gemm_p(
    const uint8_t* __restrict__ xt, long xtPlaneB,
    const __half* __restrict__ wt0, const __half* __restrict__ wt1,
    const __half* __restrict__ wtk, float* __restrict__ ytk,
    float* __restrict__ yt0, float* __restrict__ yt1,
    int nItems, int nQV, long ytPlane)
{
    constexpr int STAGE = 16384 * (1 + NW);
    extern __shared__ __align__(16) char dsm[];
    const uint32_t sb = s2u(dsm);
    const int t = threadIdx.x, lane = t & 31, w = t >> 5;
    const int wm = w >> 2, wn = w & 3;
    const int fp = t >> 2, fsub = (t & 3) * 2;

    const int nloc = (nItems - blockIdx.x + gridDim.x - 1) / gridDim.x;
    if (nloc <= 0) return;
    const int totalP = nloc * KITERS;

    auto issue = [&](int p) {
        const int j = p / KITERS, it = p % KITERS;
        const int item = blockIdx.x + j * (int)gridDim.x;
        int comp; long tileB0; bool kit = false;
        const __half* wA0 = wt0;
        if (MAP == 0) {
            if (item < nQV) { comp = item >> 6; tileB0 = (long)(item & 63) * 128; }
            else {
                int i2 = item - nQV; comp = i2 >> 3; int tb = i2 & 7;
                tileB0 = (long)(tb >> 1) * 2048 + (tb & 1) * 128;
                kit = true; wA0 = wtk;
            }
        } else { comp = item >> 3; tileB0 = (long)(item & 7) * 128; }
        const uint32_t bufB = sb + (p & 3) * STAGE;
        const uint32_t bufA = bufB + 16384;
        const uint8_t* srcB = xt + (long)comp * xtPlaneB + ((tileB0 + fp) * KITERS + it) * 128;
#pragma unroll
        for (int i = 0; i < 2; i++) {
            int q = fsub + i;
            cp16(bufB + fp * 128 + ((q ^ (fp & 7)) << 4), srcB + q * 16);
        }
        const long aoff = ((long)(comp * KITERS + it) * 128 + fp) * 64;
#pragma unroll
        for (int s = 0; s < NW; s++) {
            if (s == 1 && kit) break;
            const uint8_t* srcA = (const uint8_t*)((s ? wt1 : wA0) + aoff);
#pragma unroll
            for (int i = 0; i < 2; i++) {
                int q = fsub + i;
                cp16(bufA + s * 16384 + fp * 128 + ((q ^ (fp & 7)) << 4), srcA + q * 16);
            }
        }
    };

    float acc[NW][2][4][4];
    uint32_t acch[NW][2][4][2];
#pragma unroll
    for (int s = 0; s < NW; s++)
#pragma unroll
        for (int i = 0; i < 2; i++)
#pragma unroll
            for (int jj = 0; jj < 4; jj++) {
#pragma unroll
                for (int r = 0; r < 4; r++) acc[s][i][jj][r] = 0.f;
                acch[s][i][jj][0] = 0u; acch[s][i][jj][1] = 0u;
            }

#pragma unroll
    for (int p = 0; p < 3; p++) { issue(p); cp_commit(); }

    for (int j = 0; j < nloc; j++) {
        const int item = blockIdx.x + j * (int)gridDim.x;
        const bool kit = (MAP == 0) && (item >= nQV);
        for (int it = 0; it < KITERS; it++) {
            const int p = j * KITERS + it;
            asm volatile("cp.async.wait_group 2;" ::: "memory");
            __syncthreads();
            const uint32_t bufB = sb + (p & 3) * STAGE;
            const uint32_t bufA = bufB + 16384;
#pragma unroll
            for (int ks = 0; ks < 2; ks++) {
                uint32_t Bh[2][4], Bl[2][4];
#pragma unroll
                for (int g = 0; g < 2; g++) {
                    int pp = wn * 32 + g * 16 + (lane & 15);
                    uint32_t rb = bufB + pp * 128;
                    int p7 = pp & 7, qh = ks * 2 + (lane >> 4);
                    ldm4(rb + ((qh ^ p7) << 4), Bh[g]);
                    ldm4(rb + (((qh + 4) ^ p7) << 4), Bl[g]);
                }
#pragma unroll
                for (int s = 0; s < NW; s++) {
                    if (s == 1 && kit) break;
#pragma unroll
                    for (int i = 0; i < 2; i++) {
                        int r = wm * 32 + i * 16 + (lane & 15);
                        uint32_t ra = bufA + s * 16384 + r * 128;
                        int r7 = r & 7, qh = ks * 2 + (lane >> 4);
                        uint32_t Ah[4], Al[4];
                        ldm4(ra + ((qh ^ r7) << 4), Ah);
                        ldm4(ra + (((qh + 4) ^ r7) << 4), Al);
#pragma unroll
                        for (int jj = 0; jj < 4; jj++) {
                            int g = jj >> 1, rs = jj & 1;
                            mma_f32(acc[s][i][jj], Ah, Bh[g][rs], Bh[g][rs + 2]);
                            mma_f16(acch[s][i][jj], Ah, Bl[g][rs], Bl[g][rs + 2]);
                            mma_f16(acch[s][i][jj], Al, Bh[g][rs], Bh[g][rs + 2]);
                        }
                    }
                }
            }
            if (p + 3 < totalP) issue(p + 3);
            cp_commit();
        }

        // ---- epilogue (buffer 3 free for staging); cross terms scaled back by LO_INV ----
        {
            int comp; long ytTile0;
            float* dst0 = yt0; float* dst1 = yt1; long plane = ytPlane;
            if (MAP == 0 && kit) {
                int i2 = item - nQV; comp = i2 >> 3; ytTile0 = (long)(i2 & 7) * 128;
                dst0 = ytk; plane = YTK_PLANE;
            } else if (MAP == 0) { comp = item >> 6; ytTile0 = (long)(item & 63) * 128; }
            else { comp = item >> 3; ytTile0 = (long)(item & 7) * 128; }
            float* stage = (float*)(dsm + 3 * STAGE);
#pragma unroll
            for (int s = 0; s < NW; s++) {
                if (s == 1 && kit) break;
                float* ytS = (s ? dst1 : dst0) + (long)comp * plane + ytTile0 * 128;
#pragma unroll
                for (int pass = 0; pass < 4; pass++) {
                    __syncthreads();
                    if (wn == pass) {
#pragma unroll
                        for (int i = 0; i < 2; i++) {
                            int m = wm * 32 + i * 16 + (lane >> 2);
#pragma unroll
                            for (int jj = 0; jj < 4; jj++) {
                                int nn = jj * 8 + (lane & 3) * 2;
                                __half2 c01 = *(__half2*)&acch[s][i][jj][0];
                                __half2 c23 = *(__half2*)&acch[s][i][jj][1];
                                stage[nn * 132 + m]           = acc[s][i][jj][0] + __low2float(c01) * LO_INV;
                                stage[(nn + 1) * 132 + m]     = acc[s][i][jj][1] + __high2float(c01) * LO_INV;
                                stage[nn * 132 + m + 8]       = acc[s][i][jj][2] + __low2float(c23) * LO_INV;
                                stage[(nn + 1) * 132 + m + 8] = acc[s][i][jj][3] + __high2float(c23) * LO_INV;
                            }
                        }
                    }
                    __syncthreads();
#pragma unroll
                    for (int kk = 0; kk < 2; kk++) {
                        int idx = t + kk * 512;
                        int r = idx >> 5, q = idx & 31;
                        *(float4*)(ytS + (long)(pass * 32 + r) * 128 + q * 4) =
                            *(float4*)(stage + r * 132 + q * 4);
                    }
                }
            }
            __syncthreads();
#pragma unroll
            for (int s = 0; s < NW; s++)
#pragma unroll
                for (int i = 0; i < 2; i++)
#pragma unroll
                    for (int jj = 0; jj < 4; jj++) {
#pragma unroll
                        for (int r = 0; r < 4; r++) acc[s][i][jj][r] = 0.f;
                        acch[s][i][jj][0] = 0u; acch[s][i][jj][1] = 0u;
                    }
        }
    }
}

// ---- F(4,3) inverse transform of 36 comps -> 16 pixels (register-resident) ----
__device__ __forceinline__ void inv36(const float* __restrict__ Y, long plane, float* o) {
    float y[36];
#pragma unroll
    for (int c = 0; c < 36; c++) y[c] = __ldg(Y + c * plane);
    float Z[4][6];
#pragma unroll
    for (int c = 0; c < 6; c++) {
        float a0 = y[c], a1 = y[6 + c], a2 = y[12 + c],
              a3 = y[18 + c], a4 = y[24 + c], a5 = y[30 + c];
        Z[0][c] = a0 + a1 + a2 + a3 + a4;
        Z[1][c] = a1 - a2 + 2.f * a3 - 2.f * a4;
        Z[2][c] = a1 + a2 + 4.f * a3 + 4.f * a4;
        Z[3][c] = a1 - a2 + 8.f * a3 - 8.f * a4 + a5;
    }
#pragma unroll
    for (int a = 0; a < 4; a++) {
        float z0 = Z[a][0], z1 = Z[a][1], z2 = Z[a][2],
              z3 = Z[a][3], z4 = Z[a][4], z5 = Z[a][5];
        o[a * 4 + 0] = z0 + z1 + z2 + z3 + z4;
        o[a * 4 + 1] = z1 - z2 + 2.f * z3 - 2.f * z4;
        o[a * 4 + 2] = z1 + z2 + 4.f * z3 + 4.f * z4;
        o[a * 4 + 3] = z1 - z2 + 8.f * z3 - 8.f * z4 + z5;
    }
}

// ---- fused inverse-transform + attention -> pooled fp32 pixel-major ----
__global__ __launch_bounds__(256) void attn_wino(
    const float* __restrict__ yt, const float* __restrict__ ytk,
    float* __restrict__ gp)
{
    __shared__ float sdots[2][4][16];
    __shared__ float fdots[2][16];
    __shared__ float stage[2][16][128];
    const int t = threadIdx.x, lane = t & 31;
    const int oc = t & 127, tl = t >> 7;
    const int wsub = (t >> 5) & 3;
    const int b = blockIdx.x >> 7, tp = blockIdx.x & 127;
    const int tloc = tp * 2 + tl;

    float k16[16];
    inv36(ytk + (long)(b * 256 + tloc) * 128 + oc, YTK_PLANE, k16);

    float m[16], s[16], acc[16];

    for (int f = 0; f < 8; f++) {
        const long tg = ((long)((b * 8 + f) * 256 + tloc)) * 128 + oc;
        float q16[16];
        inv36(yt + tg, YT_PLANE, q16);
        float p[16];
#pragma unroll
        for (int px = 0; px < 16; px++) p[px] = q16[px] * k16[px];
#pragma unroll
        for (int off = 16; off; off >>= 1)
#pragma unroll
            for (int px = 0; px < 16; px++) p[px] += __shfl_xor_sync(0xFFFFFFFFu, p[px], off);
        if (lane == 0)
#pragma unroll
            for (int px = 0; px < 16; px++) sdots[tl][wsub][px] = p[px];
        __syncthreads();
        if (t < 32) {
            int t2 = t >> 4, px = t & 15;
            fdots[t2][px] = sdots[t2][0][px] + sdots[t2][1][px] + sdots[t2][2][px] + sdots[t2][3][px];
        }
        float v16[16];
        inv36(yt + YT_SET + tg, YT_PLANE, v16);
        __syncthreads();
#pragma unroll
        for (int px = 0; px < 16; px++) {
            float d = fdots[tl][px];
            if (f == 0) { m[px] = d; s[px] = 1.f; acc[px] = v16[px]; }
            else {
                float nm = fmaxf(m[px], d);
                float sc = expf(m[px] - nm);
                float e  = expf(d - nm);
                s[px] = s[px] * sc + e;
                acc[px] = acc[px] * sc + e * v16[px];
                m[px] = nm;
            }
        }
    }

#pragma unroll
    for (int px = 0; px < 16; px++) stage[tl][px][oc] = acc[px] / s[px];
    __syncthreads();
    for (int idx = t; idx < 2 * 16 * 32; idx += 256) {
        int l = idx & 31, px = (idx >> 5) & 15, tt = idx >> 9;
        int tw = tp * 2 + tt;
        int ty = tw >> 4, tx = tw & 15;
        int pix = (4 * ty + (px >> 2)) * 64 + 4 * tx + (px & 3);
        float4 v = *(float4*)&stage[tt][px][l * 4];
        *(float4*)(gp + ((long)(b * HW + pix)) * 128 + l * 4) = v;
    }
}

// ---- final: inverse transform + bias + T-broadcast, full-row staged stores ----
__global__ __launch_bounds__(256) void wino_out_final(
    const float* __restrict__ yto, const float* __restrict__ bias, float* __restrict__ out)
{
    extern __shared__ float st[];   // [4 rows][64 cols][128 oc] = 128KB
    const int b = blockIdx.x >> 5, rest = blockIdx.x & 31;
    const int ty = rest >> 1, half = rest & 1;
    const int t = threadIdx.x;
    const int oc = t & 127, tl = t >> 7;

    for (int pass = 0; pass < 8; pass++) {
        int tx = pass * 2 + tl;
        long tile = (long)b * 256 + ty * 16 + tx;
        const float* Y = yto + (long)half * YTO_HALF + tile * 128 + oc;
        float o[16];
        inv36(Y, YTO_PLANE, o);
#pragma unroll
        for (int px = 0; px < 16; px++)
            st[((px >> 2) * 64 + tx * 4 + (px & 3)) * 128 + oc] = o[px];
    }
    __syncthreads();

    for (int u = t; u < 512; u += 256) {
        int oc2 = u & 127, row = u >> 7;
        float bv = bias[half * 128 + oc2];
        float4 rv[16];
#pragma unroll
        for (int c4 = 0; c4 < 16; c4++) {
            rv[c4].x = st[(row * 64 + c4 * 4 + 0) * 128 + oc2] + bv;
            rv[c4].y = st[(row * 64 + c4 * 4 + 1) * 128 + oc2] + bv;
            rv[c4].z = st[(row * 64 + c4 * 4 + 2) * 128 + oc2] + bv;
            rv[c4].w = st[(row * 64 + c4 * 4 + 3) * 128 + oc2] + bv;
        }
#pragma unroll
        for (int tt = 0; tt < 8; tt++) {
            float* op = out + ((long)(b * 8 + tt) * 256 + half * 128 + oc2) * HW
                        + (ty * 4 + row) * 64;
#pragma unroll
            for (int c4 = 0; c4 < 16; c4++)
                *(float4*)(op + c4 * 4) = rv[c4];
        }
    }
}

// ---------------------------------------------------------------------------
extern "C" void kernel_launch(void* const* d_in, const int* in_sizes, int n_in,
                              void* d_out, int out_size)
{
    const float* x     = (const float*)d_in[0];
    const float* w_k   = (const float*)d_in[1];
    const float* w_q   = (const float*)d_in[2];
    const float* w_v   = (const float*)d_in[3];
    const float* w_out = (const float*)d_in[4];
    const float* b_out = (const float*)d_in[5];
    float* out = (float*)d_out;

    void* basev = nullptr;
    cudaGetSymbolAddress(&basev, g_scratch);
    float* S = (float*)basev;
    float* gp = S + OFF_GP;
    __half* wtO0 = (__half*)(S + OFF_WTO0);
    __half* wtO1 = (__half*)(S + OFF_WTO1);
    __half* wtq  = (__half*)(S + OFF_WTQ);
    __half* wtv  = (__half*)(S + OFF_WTV);
    __half* wtk  = (__half*)(S + OFF_WTK);
    uint8_t* xtp = (uint8_t*)(S + OFF_XTP);
    float*   yto = S + OFF_YTO;
    uint8_t* xt  = (uint8_t*)(S + OFF_XT);
    float*   yt  = S + OFF_YT;
    float*   ytk = S + OFF_YTK;

    const int DSM2 = 4 * 49152;
    const int DSMW = 32 * 6 * 67 * 4;
    const int DSMF = 4 * 64 * 128 * 4;
    cudaFuncSetAttribute(wino_gemm_p<2, 8, 0>, cudaFuncAttributeMaxDynamicSharedMemorySize, DSM2);
    cudaFuncSetAttribute(wino_gemm_p<2, 4, 2>, cudaFuncAttributeMaxDynamicSharedMemorySize, DSM2);
    cudaFuncSetAttribute(wino_in,   cudaFuncAttributeMaxDynamicSharedMemorySize, DSMW);
    cudaFuncSetAttribute(wino_in_p, cudaFuncAttributeMaxDynamicSharedMemorySize, DSMW);
    cudaFuncSetAttribute(wino_out_final, cudaFuncAttributeMaxDynamicSharedMemorySize, DSMF);

    // all weight transforms in one launch
    wino_w_all<<<512, 256>>>(w_q, w_v, w_k, w_out, wtq, wtv, wtk, wtO0, wtO1);
    wino_in<<<dim3(16, 32), 256, DSMW>>>(x, xt);

    // merged q+v (2304) + k (288) persistent Winograd GEMM, 512 threads
    wino_gemm_p<2, 8, 0><<<148, 512, DSM2>>>(
        xt, XT_PLANE_B, wtq, wtv, wtk, ytk, yt, yt + YT_SET, 2592, 2304, YT_PLANE);

    // fused inverse transform + attention -> pooled fp32 pixel-major
    attn_wino<<<512, 256>>>(yt, ytk, gp);

    // out conv via Winograd
    wino_in_p<<<dim3(16, 4), 256, DSMW>>>(gp, xtp);
    wino_gemm_p<2, 4, 2><<<148, 512, DSM2>>>(
        xtp, XTP_PLANE_B, wtO0, wtO1, nullptr, nullptr, yto, yto + YTO_HALF, 288, 288, YTO_PLANE);
    wino_out_final<<<128, 256, DSMF>>>(yto, b_out, out);
}